// round 16
// baseline (speedup 1.0000x reference)
#include <cuda_runtime.h>
#include <cuda_fp16.h>
#include <cstdint>

// Problem: B=2, H=16, S=2048, D=128, fp32 in/out, int32 mask over keys.
// Masked keys (~50%) contribute exactly zero -> K/V compacted in prep.
// Padding slots are ZERO rows: p = 2^0 = 1 exactly, contributes 0 to O;
// exact pad count subtracted from l in the epilogue.
// Config (validated R8/R15): BM=64, BN=64, Q-in-regs, 3 CTAs/SM, cp.async.ca,
// row-major V via ldmatrix.trans, gather-only prep.
// This round: softmax via h2exp2 (ex2.approx.f16x2) — halves MUFU ops and
// produces the fp16 PV A-fragment directly (no separate pack).
constexpr int Bc = 2, Hh = 16, Ss = 2048, Dd = 128;
constexpr int BM = 64;          // queries per block (4 warps x 16 rows)
constexpr int BN = 64;          // keys per tile
constexpr int NT = 128;         // threads
constexpr float QSCALE = 0.08838834764831845f * 1.4426950408889634f; // /sqrt(128)*log2(e)

constexpr int KTILEB = 64 * 256;    // 16384 (64 keys x 128 fp16, XOR-swizzled rows)
constexpr int VTILEB = 64 * 256;    // 16384 (same layout as K; consumed via trans)
constexpr int STAGEB = KTILEB + VTILEB;  // 32768
constexpr int NSTAGE = 2;                // 65536 B -> 3 CTAs/SM

// fp16 operands, compacted row-major [bh][j][d] (zeros at padding)
__device__ __align__(16) __half g_kh[(size_t)Bc * Hh * Ss * Dd];
__device__ __align__(16) __half g_vh[(size_t)Bc * Hh * Ss * Dd];

__device__ __forceinline__ uint32_t f2h2(float lo, float hi) {
    __half2 h = __floats2half2_rn(lo, hi);
    return *(uint32_t*)&h;
}

__device__ __forceinline__ void mma16(float* d, uint32_t a0, uint32_t a1, uint32_t a2,
                                      uint32_t a3, uint32_t b0, uint32_t b1) {
    asm volatile(
        "mma.sync.aligned.m16n8k16.row.col.f32.f16.f16.f32 "
        "{%0,%1,%2,%3},{%4,%5,%6,%7},{%8,%9},{%0,%1,%2,%3};"
        : "+f"(d[0]), "+f"(d[1]), "+f"(d[2]), "+f"(d[3])
        : "r"(a0), "r"(a1), "r"(a2), "r"(a3), "r"(b0), "r"(b1));
}

__device__ __forceinline__ void ldsm4(uint32_t& t0, uint32_t& t1, uint32_t& t2,
                                      uint32_t& t3, uint32_t addr) {
    asm volatile("ldmatrix.sync.aligned.m8n8.x4.shared.b16 {%0,%1,%2,%3}, [%4];"
                 : "=r"(t0), "=r"(t1), "=r"(t2), "=r"(t3) : "r"(addr));
}
__device__ __forceinline__ void ldsm4t(uint32_t& t0, uint32_t& t1, uint32_t& t2,
                                       uint32_t& t3, uint32_t addr) {
    asm volatile("ldmatrix.sync.aligned.m8n8.x4.trans.shared.b16 {%0,%1,%2,%3}, [%4];"
                 : "=r"(t0), "=r"(t1), "=r"(t2), "=r"(t3) : "r"(addr));
}

__device__ __forceinline__ void cp16(uint32_t dst, const void* src) {
    asm volatile("cp.async.ca.shared.global [%0], [%1], 16;" :: "r"(dst), "l"(src));
}
#define CP_COMMIT() asm volatile("cp.async.commit_group;" ::: "memory")

// ---------------- prep: scan (recomputed per block) + gather + fp16 convert ----
// No transpose anywhere: K and V both written row-major compacted.
__global__ void __launch_bounds__(256) prep_kernel(const float* __restrict__ k,
                                                   const float* __restrict__ v,
                                                   const int* __restrict__ mask) {
    __shared__ int wcnt[64], woff[64];
    __shared__ int sidx[64];
    __shared__ int s_ntrue;
    const int t = blockIdx.x, bh = blockIdx.y, tid = threadIdx.x;
    const int b = bh >> 4;
    const int warp = tid >> 5, lane = tid & 31;

    for (int ch = warp; ch < 64; ch += 8) {
        int m = mask[b * Ss + ch * 32 + lane] != 0;
        unsigned bal = __ballot_sync(0xffffffffu, m);
        if (lane == 0) wcnt[ch] = __popc(bal);
    }
    __syncthreads();
    if (tid == 0) {
        int s = 0;
        for (int i = 0; i < 64; i++) { woff[i] = s; s += wcnt[i]; }
        s_ntrue = s;
    }
    __syncthreads();
    const int ntrue = s_ntrue;
    const int npad = (ntrue + 63) & ~63;
    if (t * 64 >= npad) return;
    const int base = t * 64;

    if (tid < 64) sidx[tid] = -1;   // -1 => zero padding row
    __syncthreads();
    for (int ch = warp; ch < 64; ch += 8) {
        int src = ch * 32 + lane;
        int m = mask[b * Ss + src] != 0;
        unsigned bal = __ballot_sync(0xffffffffu, m);
        if (m) {
            int pos = woff[ch] + __popc(bal & ((1u << lane) - 1u));
            if (pos >= base && pos < base + 64) sidx[pos - base] = src;
        }
    }
    __syncthreads();

    const float* kg = k + (size_t)bh * Ss * Dd;
    const float* vg = v + (size_t)bh * Ss * Dd;
    uint32_t* ko = (uint32_t*)(g_kh + ((size_t)bh * Ss + base) * Dd);
    uint32_t* vo = (uint32_t*)(g_vh + ((size_t)bh * Ss + base) * Dd);

    for (int i = tid; i < 64 * 32; i += 256) {
        int r = i >> 5, c4 = (i & 31) << 2;
        int idx = sidx[r];
        float4 x = (idx >= 0) ? *(const float4*)(kg + (size_t)idx * Dd + c4)
                              : make_float4(0.f, 0.f, 0.f, 0.f);
        ko[(r * Dd + c4) >> 1] = f2h2(x.x, x.y);
        ko[((r * Dd + c4) >> 1) + 1] = f2h2(x.z, x.w);
        float4 y = (idx >= 0) ? *(const float4*)(vg + (size_t)idx * Dd + c4)
                              : make_float4(0.f, 0.f, 0.f, 0.f);
        vo[(r * Dd + c4) >> 1] = f2h2(y.x, y.y);
        vo[((r * Dd + c4) >> 1) + 1] = f2h2(y.z, y.w);
    }
}

// ---------------- main kernel ----------------
// dyn smem: 2 x (K 16384 + V 16384) = 65536 B -> 3 CTAs/SM (regs <= 170)
__global__ void __launch_bounds__(NT, 3)
fa_kernel(const float* __restrict__ q, const int* __restrict__ mask,
          float* __restrict__ out) {
    extern __shared__ char sm[];
    __shared__ int red[4];
    const uint32_t sbase = (uint32_t)__cvta_generic_to_shared(sm);

    const int tid = threadIdx.x, warp = tid >> 5, lane = tid & 31;
    const int g = lane >> 2, tig = lane & 3;
    const int qb = blockIdx.x, bh = blockIdx.y, b = bh >> 4;  // Hh=16
    const size_t bh_base = (size_t)bh * Ss * Dd;

    const __half* ksrc = g_kh + (size_t)bh * Ss * Dd;
    const __half* vsrc = g_vh + (size_t)bh * Ss * Dd;

    auto issue_tile = [&](int t, int bi) {
        const uint32_t Ka = sbase + bi * STAGEB;
        const uint32_t Va = Ka + KTILEB;
        const __half* ks = ksrc + (size_t)t * BN * Dd;
        const __half* vs = vsrc + (size_t)t * BN * Dd;
#pragma unroll
        for (int i = 0; i < 8; i++) {          // K: 64 rows x 16 chunks of 16B
            int ch = tid + i * NT;
            int r = ch >> 4, c = ch & 15;
            cp16(Ka + r * 256 + ((c ^ (r & 7)) << 4), ks + r * Dd + c * 8);
        }
#pragma unroll
        for (int i = 0; i < 8; i++) {          // V: same layout
            int ch = tid + i * NT;
            int r = ch >> 4, c = ch & 15;
            cp16(Va + r * 256 + ((c ^ (r & 7)) << 4), vs + r * Dd + c * 8);
        }
        CP_COMMIT();
    };

    // count unmasked keys (mask is 8KB, L2-hot)
    int cnt = 0;
    for (int i = tid; i < Ss; i += NT) cnt += (mask[b * Ss + i] != 0);
#pragma unroll
    for (int s = 16; s > 0; s >>= 1) cnt += __shfl_xor_sync(0xffffffffu, cnt, s);
    if (lane == 0) red[warp] = cnt;

    issue_tile(0, 0);

    // Q fragments straight from global (one-time, pre-scaled fp16, in regs)
    const float* qg = q + bh_base + (size_t)qb * BM * Dd;
    const int r0 = warp * 16 + g, r1 = r0 + 8;
    uint32_t qf[8][4];
#pragma unroll
    for (int kk = 0; kk < 8; kk++) {
        float2 a = *(const float2*)(qg + (size_t)r0 * Dd + kk * 16 + 2 * tig);
        float2 bq = *(const float2*)(qg + (size_t)r1 * Dd + kk * 16 + 2 * tig);
        float2 c = *(const float2*)(qg + (size_t)r0 * Dd + kk * 16 + 2 * tig + 8);
        float2 d = *(const float2*)(qg + (size_t)r1 * Dd + kk * 16 + 2 * tig + 8);
        qf[kk][0] = f2h2(a.x * QSCALE, a.y * QSCALE);
        qf[kk][1] = f2h2(bq.x * QSCALE, bq.y * QSCALE);
        qf[kk][2] = f2h2(c.x * QSCALE, c.y * QSCALE);
        qf[kk][3] = f2h2(d.x * QSCALE, d.y * QSCALE);
    }
    __syncthreads();   // red visible
    const int ntrue = red[0] + red[1] + red[2] + red[3];
    const int ntiles = (ntrue + BN - 1) >> 6;
    const float padf = (float)(ntiles * BN - ntrue);

    if (1 < ntiles) issue_tile(1, 1);

    // ldmatrix lane addressing (x4): mi = matrix group, mrow = row in matrix
    const int mi = lane >> 3, mrow = lane & 7;
    // K B-frags (non-trans): rows = key octets via mi>>1, chunk low bit = mi&1
    const uint32_t krow = (uint32_t)((8 * (mi >> 1) + mrow) * 256);
    const int cbase = mi & 1;
    // V B-frags (trans): rows = key rows (kt*16 + (mi&1)*8 + mrow), chunk = 2np + (mi>>1)
    const uint32_t vrow_t = (uint32_t)(((mi & 1) * 8 + mrow) * 256);
    const int vchi = mi >> 1;

    float oa[16][4];
#pragma unroll
    for (int n = 0; n < 16; n++)
        oa[n][0] = oa[n][1] = oa[n][2] = oa[n][3] = 0.f;
    float l0 = 0.f, l1 = 0.f;

#pragma unroll 1
    for (int t = 0; t < ntiles; t++) {
        const int bi = t & 1;
        asm volatile("cp.async.wait_group 0;" ::: "memory");
        __syncthreads();             // tile t visible; buffer bi^1 free (t-1 done)
        if (t + 1 < ntiles) issue_tile(t + 1, bi ^ 1);

        const uint32_t kb = sbase + bi * STAGEB + krow;
        const uint32_t vbt = sbase + bi * STAGEB + KTILEB + vrow_t;

        // ---- S = (Q*scale*log2e) K^T ----
        float sa[8][4];
#pragma unroll
        for (int j = 0; j < 8; j++)
            sa[j][0] = sa[j][1] = sa[j][2] = sa[j][3] = 0.f;
#pragma unroll
        for (int kk = 0; kk < 8; kk++) {
            const uint32_t kch = (uint32_t)(((kk * 2 + cbase) ^ mrow) << 4);
#pragma unroll
            for (int jp = 0; jp < 4; jp++) {
                uint32_t t0, t1, t2, t3;
                ldsm4(t0, t1, t2, t3, kb + jp * 4096 + kch);
                mma16(sa[2 * jp], qf[kk][0], qf[kk][1], qf[kk][2], qf[kk][3], t0, t1);
                mma16(sa[2 * jp + 1], qf[kk][0], qf[kk][1], qf[kk][2], qf[kk][3], t2, t3);
            }
        }

        // ---- p = 2^s in fp16 (ex2.approx.f16x2): one MUFU per element pair,
        //      result IS the PV A-fragment. Padding rows: s=0 -> p=1 exactly.
        uint32_t ph0[8], ph1[8];
#pragma unroll
        for (int j = 0; j < 8; j++) {
            __half2 s01 = __floats2half2_rn(sa[j][0], sa[j][1]);
            __half2 s23 = __floats2half2_rn(sa[j][2], sa[j][3]);
            __half2 p01 = h2exp2(s01);
            __half2 p23 = h2exp2(s23);
            ph0[j] = *(uint32_t*)&p01;
            ph1[j] = *(uint32_t*)&p23;
            float2 f01 = __half22float2(p01);
            float2 f23 = __half22float2(p23);
            l0 += f01.x + f01.y;
            l1 += f23.x + f23.y;
        }

        // ---- O += P V : V B-frags via ldmatrix.trans from row-major V ----
#pragma unroll
        for (int kt = 0; kt < 4; kt++) {       // key group of 16
            uint32_t a0 = ph0[2 * kt], a1 = ph1[2 * kt];
            uint32_t a2 = ph0[2 * kt + 1], a3 = ph1[2 * kt + 1];
            const uint32_t vb = vbt + (uint32_t)(kt * 16 * 256);
#pragma unroll
            for (int np = 0; np < 8; np++) {   // d-octet pair
                const uint32_t vch = (uint32_t)(((2 * np + vchi) ^ mrow) << 4);
                uint32_t t0, t1, t2, t3;
                ldsm4t(t0, t1, t2, t3, vb + vch);
                mma16(oa[2 * np], a0, a1, a2, a3, t0, t1);
                mma16(oa[2 * np + 1], a0, a1, a2, a3, t2, t3);
            }
        }
    }

    // ---- epilogue: quad-reduce l, subtract exact padding count, store ----
    l0 += __shfl_xor_sync(0xffffffffu, l0, 1);
    l0 += __shfl_xor_sync(0xffffffffu, l0, 2);
    l1 += __shfl_xor_sync(0xffffffffu, l1, 1);
    l1 += __shfl_xor_sync(0xffffffffu, l1, 2);
    const float i0 = 1.f / (l0 - padf), i1 = 1.f / (l1 - padf);
    float* og = out + bh_base + (size_t)qb * BM * Dd;
#pragma unroll
    for (int n = 0; n < 16; n++) {
        int c = n * 8 + 2 * tig;
        *(float2*)(og + (size_t)r0 * Dd + c) = make_float2(oa[n][0] * i0, oa[n][1] * i0);
        *(float2*)(og + (size_t)r1 * Dd + c) = make_float2(oa[n][2] * i1, oa[n][3] * i1);
    }
}

extern "C" void kernel_launch(void* const* d_in, const int* in_sizes, int n_in,
                              void* d_out, int out_size) {
    (void)in_sizes; (void)n_in; (void)out_size;
    const float* q = (const float*)d_in[0];
    const float* k = (const float*)d_in[1];
    const float* v = (const float*)d_in[2];
    const int* mask = (const int*)d_in[3];
    float* out = (float*)d_out;

    prep_kernel<<<dim3(Ss / 64, Bc * Hh), 256>>>(k, v, mask);

    constexpr int SMEM_BYTES = NSTAGE * STAGEB;  // 65536
    cudaFuncSetAttribute(fa_kernel, cudaFuncAttributeMaxDynamicSharedMemorySize,
                         SMEM_BYTES);
    fa_kernel<<<dim3(Ss / BM, Bc * Hh), NT, SMEM_BYTES>>>(q, mask, out);
}